// round 14
// baseline (speedup 1.0000x reference)
#include <cuda_runtime.h>
#include <cuda_bf16.h>
#include <cstdint>

#define NTOK 8192      // B*S
#define CCH  128       // C
#define HID  256       // 2C
#define SEQ  4096      // S per batch
#define NH   4
#define HD   32

typedef unsigned int u32;

// ---------------- scratch (static device memory, no allocs) ----------------
__device__ float g_vp [NTOK * CCH];
__device__ float g_x  [NTOK * CCH];
__device__ float g_rs1[NTOK * CCH];
__device__ float g_h  [NTOK * HID];
__device__ float g_h3 [3 * NTOK * HID];
// head-major fp16 operands: [b*NH+h][token][16 u32]
__device__ u32 g_qf[2 * NH * SEQ * 16];
__device__ u32 g_kf[2 * NH * SEQ * 16];
__device__ u32 g_vf[2 * NH * SEQ * 16];

struct Ptrs3  { const float* p[3]; };
struct LNIn   { const float* x[3]; const float* g[3]; const float* b[3]; };
struct QKVOut { u32* o16[3]; float sc[3]; float* vC; };

// ---------------- helpers -----------------------------------------------------
__device__ __forceinline__ u32 packhf(float x, float y) {      // fp16x2, x->low
    u32 d; asm("cvt.rn.f16x2.f32 %0,%2,%1;" : "=r"(d) : "f"(x), "f"(y)); return d;
}
__device__ __forceinline__ float exf(float x) {                // MUFU exp2
    float r; asm("ex2.approx.f32 %0,%1;" : "=f"(r) : "f"(x)); return r;
}
__device__ __forceinline__ u32 sptr(const void* p) {
    u32 a; asm("{.reg .u64 t; cvta.to.shared.u64 t,%1; cvt.u32.u64 %0,t;}" : "=r"(a) : "l"(p));
    return a;
}
__device__ __forceinline__ void mma16816h(float* c, const u32* a, const u32* b) {
    asm volatile(
        "mma.sync.aligned.m16n8k16.row.col.f32.f16.f16.f32 "
        "{%0,%1,%2,%3},{%4,%5,%6,%7},{%8,%9},{%0,%1,%2,%3};"
        : "+f"(c[0]), "+f"(c[1]), "+f"(c[2]), "+f"(c[3])
        : "r"(a[0]), "r"(a[1]), "r"(a[2]), "r"(a[3]), "r"(b[0]), "r"(b[1]));
}
__device__ __forceinline__ void ldsm4(u32& r0, u32& r1, u32& r2, u32& r3, u32 addr) {
    asm volatile("ldmatrix.sync.aligned.m8n8.x4.shared.b16 {%0,%1,%2,%3},[%4];"
                 : "=r"(r0), "=r"(r1), "=r"(r2), "=r"(r3) : "r"(addr));
}
__device__ __forceinline__ void ldsm4t(u32& r0, u32& r1, u32& r2, u32& r3, u32 addr) {
    asm volatile("ldmatrix.sync.aligned.m8n8.x4.trans.shared.b16 {%0,%1,%2,%3},[%4];"
                 : "=r"(r0), "=r"(r1), "=r"(r2), "=r"(r3) : "r"(addr));
}

// ==================== fully-resident fp16 GEMM ================================
// Stage all of A[128,K] and B[K,64] in smem upfront; no barriers in K loop.
// A image: row stride AST = K/2+4 u32 (272B/528B, bank-shift 4 => ldsm clean).
// B image: K/16 tiles of [16][36] u32 (144B rows).
template <int K, bool LEAKY, bool RES, bool TRANS>
__global__ __launch_bounds__(128, 2) void gemm_rk(
    const float* __restrict__ A, const float* __restrict__ Bw,
    const float* __restrict__ bias, const float* __restrict__ res,
    float* __restrict__ C, int M)
{
    constexpr int AST = K / 2 + 4;
    constexpr int NKT = K / 16;
    extern __shared__ __align__(16) u32 dsm[];
    u32* sAf = dsm;                       // 128*AST u32
    u32* sB  = dsm + 128 * AST;           // NKT*576 u32

    const int tid  = threadIdx.x;
    const int lane = tid & 31;
    const int w    = tid >> 5;
    const int n0 = blockIdx.y * 128;
    const int m0 = blockIdx.x * 64;
    const int g  = lane >> 3;
    const int lr = lane & 7;

    // ---- stage A (whole K) --------------------------------------------------
    #pragma unroll 8
    for (int it = 0; it < K / 4; it++) {
        int idx  = tid + it * 128;
        int row  = idx / (K / 4);
        int colq = idx % (K / 4);
        float4 f = *reinterpret_cast<const float4*>(&A[(size_t)(n0 + row) * K + colq * 4]);
        sAf[row * AST + colq * 2]     = packhf(f.x, f.y);
        sAf[row * AST + colq * 2 + 1] = packhf(f.z, f.w);
    }
    // ---- stage B (whole K) --------------------------------------------------
    #pragma unroll 8
    for (int it = 0; it < K / 8; it++) {
        int idx  = tid + it * 128;
        int krow = idx >> 4;
        int bcol = idx & 15;
        float4 f = *reinterpret_cast<const float4*>(&Bw[(size_t)krow * M + m0 + bcol * 4]);
        int o = (krow >> 4) * 576 + (krow & 15) * 36 + bcol * 2;
        sB[o]     = packhf(f.x, f.y);
        sB[o + 1] = packhf(f.z, f.w);
    }
    __syncthreads();

    // ---- compute (no barriers) ----------------------------------------------
    const u32 aS = sptr(sAf);
    const u32 bS = sptr(sB);
    u32 aBase[2];
    #pragma unroll
    for (int mi = 0; mi < 2; mi++)
        aBase[mi] = aS + (u32)((w * 32 + mi * 16 + (g & 1) * 8 + lr) * (AST * 4) + (g >> 1) * 16);
    const u32 bBase = bS + (u32)((8 * (g & 1) + lr) * 144);

    float c[2][8][4];
    #pragma unroll
    for (int mi = 0; mi < 2; mi++)
        #pragma unroll
        for (int nt = 0; nt < 8; nt++)
            #pragma unroll
            for (int e = 0; e < 4; e++) c[mi][nt][e] = 0.f;

    #pragma unroll
    for (int t = 0; t < NKT; t++) {
        u32 aF[2][4];
        #pragma unroll
        for (int mi = 0; mi < 2; mi++)
            ldsm4(aF[mi][0], aF[mi][1], aF[mi][2], aF[mi][3], aBase[mi] + t * 32);
        u32 bF[8][2];
        #pragma unroll
        for (int dp = 0; dp < 4; dp++)
            ldsm4t(bF[2 * dp][0], bF[2 * dp][1], bF[2 * dp + 1][0], bF[2 * dp + 1][1],
                   bBase + t * 2304 + (dp * 16 + 8 * (g >> 1)) * 2);
        #pragma unroll
        for (int mi = 0; mi < 2; mi++)
            #pragma unroll
            for (int nt = 0; nt < 8; nt++)
                mma16816h(c[mi][nt], aF[mi], bF[nt]);
    }

    // ---- epilogue -------------------------------------------------------------
    #pragma unroll
    for (int mi = 0; mi < 2; mi++) {
        int r0 = n0 + w * 32 + mi * 16 + (lane >> 2);
        #pragma unroll
        for (int nt = 0; nt < 8; nt++) {
            int col = m0 + nt * 8 + (lane & 3) * 2;
            float2 bb = *reinterpret_cast<const float2*>(&bias[col]);
            float v0 = c[mi][nt][0] + bb.x;
            float v1 = c[mi][nt][1] + bb.y;
            float v2 = c[mi][nt][2] + bb.x;
            float v3 = c[mi][nt][3] + bb.y;
            if (LEAKY) {
                v0 = fmaxf(v0, 0.f) + 0.01f * fminf(v0, 0.f);
                v1 = fmaxf(v1, 0.f) + 0.01f * fminf(v1, 0.f);
                v2 = fmaxf(v2, 0.f) + 0.01f * fminf(v2, 0.f);
                v3 = fmaxf(v3, 0.f) + 0.01f * fminf(v3, 0.f);
            }
            if (RES) {
                float2 r4a = *reinterpret_cast<const float2*>(&res[(size_t)r0 * M + col]);
                float2 r4b = *reinterpret_cast<const float2*>(&res[(size_t)(r0 + 8) * M + col]);
                v0 += r4a.x; v1 += r4a.y; v2 += r4b.x; v3 += r4b.y;
            }
            if (!TRANS) {
                *reinterpret_cast<float2*>(&C[(size_t)r0 * M + col])       = make_float2(v0, v1);
                *reinterpret_cast<float2*>(&C[(size_t)(r0 + 8) * M + col]) = make_float2(v2, v3);
            } else {
                int bI = r0 >> 12, sI = r0 & (SEQ - 1);
                float* dst = C + (size_t)bI * CCH * SEQ + sI;
                dst[(size_t)col * SEQ]           = v0;
                dst[(size_t)(col + 1) * SEQ]     = v1;
                dst[(size_t)col * SEQ + 8]       = v2;
                dst[(size_t)(col + 1) * SEQ + 8] = v3;
            }
        }
    }
}

// ==================== resident qkv GEMM2 (K=256, batched z) ===================
__global__ __launch_bounds__(128, 2) void gemm_rqkv(
    const float* __restrict__ Abase, long Astride,
    Ptrs3 W, Ptrs3 Bi, QKVOut qo)
{
    constexpr int K = HID, M = CCH;
    constexpr int AST = K / 2 + 4;       // 132
    constexpr int NKT = K / 16;          // 16
    extern __shared__ __align__(16) u32 dsm[];
    u32* sAf = dsm;
    u32* sB  = dsm + 128 * AST;

    const int z = blockIdx.z;
    const float* A    = Abase + (size_t)z * Astride;
    const float* Bw   = W.p[z];
    const float* bias = Bi.p[z];

    const int tid  = threadIdx.x;
    const int lane = tid & 31;
    const int w    = tid >> 5;
    const int n0 = blockIdx.y * 128;
    const int m0 = blockIdx.x * 64;
    const int g  = lane >> 3;
    const int lr = lane & 7;

    #pragma unroll 8
    for (int it = 0; it < K / 4; it++) {
        int idx  = tid + it * 128;
        int row  = idx / (K / 4);
        int colq = idx % (K / 4);
        float4 f = *reinterpret_cast<const float4*>(&A[(size_t)(n0 + row) * K + colq * 4]);
        sAf[row * AST + colq * 2]     = packhf(f.x, f.y);
        sAf[row * AST + colq * 2 + 1] = packhf(f.z, f.w);
    }
    #pragma unroll 8
    for (int it = 0; it < K / 8; it++) {
        int idx  = tid + it * 128;
        int krow = idx >> 4;
        int bcol = idx & 15;
        float4 f = *reinterpret_cast<const float4*>(&Bw[(size_t)krow * M + m0 + bcol * 4]);
        int o = (krow >> 4) * 576 + (krow & 15) * 36 + bcol * 2;
        sB[o]     = packhf(f.x, f.y);
        sB[o + 1] = packhf(f.z, f.w);
    }
    __syncthreads();

    const u32 aS = sptr(sAf);
    const u32 bS = sptr(sB);
    u32 aBase[2];
    #pragma unroll
    for (int mi = 0; mi < 2; mi++)
        aBase[mi] = aS + (u32)((w * 32 + mi * 16 + (g & 1) * 8 + lr) * (AST * 4) + (g >> 1) * 16);
    const u32 bBase = bS + (u32)((8 * (g & 1) + lr) * 144);

    float c[2][8][4];
    #pragma unroll
    for (int mi = 0; mi < 2; mi++)
        #pragma unroll
        for (int nt = 0; nt < 8; nt++)
            #pragma unroll
            for (int e = 0; e < 4; e++) c[mi][nt][e] = 0.f;

    #pragma unroll
    for (int t = 0; t < NKT; t++) {
        u32 aF[2][4];
        #pragma unroll
        for (int mi = 0; mi < 2; mi++)
            ldsm4(aF[mi][0], aF[mi][1], aF[mi][2], aF[mi][3], aBase[mi] + t * 32);
        u32 bF[8][2];
        #pragma unroll
        for (int dp = 0; dp < 4; dp++)
            ldsm4t(bF[2 * dp][0], bF[2 * dp][1], bF[2 * dp + 1][0], bF[2 * dp + 1][1],
                   bBase + t * 2304 + (dp * 16 + 8 * (g >> 1)) * 2);
        #pragma unroll
        for (int mi = 0; mi < 2; mi++)
            #pragma unroll
            for (int nt = 0; nt < 8; nt++)
                mma16816h(c[mi][nt], aF[mi], bF[nt]);
    }

    #pragma unroll
    for (int mi = 0; mi < 2; mi++) {
        int r0 = n0 + w * 32 + mi * 16 + (lane >> 2);
        #pragma unroll
        for (int nt = 0; nt < 8; nt++) {
            int col = m0 + nt * 8 + (lane & 3) * 2;
            float2 bb = *reinterpret_cast<const float2*>(&bias[col]);
            float v0 = c[mi][nt][0] + bb.x;
            float v1 = c[mi][nt][1] + bb.y;
            float v2 = c[mi][nt][2] + bb.x;
            float v3 = c[mi][nt][3] + bb.y;
            int h = col >> 5, dpair = (col & 31) >> 1;
            int bI = r0 >> 12, sI = r0 & (SEQ - 1);
            size_t oA = ((size_t)(bI * NH + h) * SEQ + sI) * 16 + dpair;
            size_t oB = oA + 8 * 16;
            u32* o16 = qo.o16[z];
            float sc = qo.sc[z];
            o16[oA] = packhf(v0 * sc, v1 * sc);
            o16[oB] = packhf(v2 * sc, v3 * sc);
            if (z == 2) {
                *reinterpret_cast<float2*>(&qo.vC[(size_t)r0 * M + col])       = make_float2(v0, v1);
                *reinterpret_cast<float2*>(&qo.vC[(size_t)(r0 + 8) * M + col]) = make_float2(v2, v3);
            }
        }
    }
}

// ==================== fused LN + GEMM1 (resident B) ===========================
// dsm: [0,65536) fp32 tile (reused for B image after LN pack) | A fp16 34816
#define LN_SMEM (65536 + 34816)

__global__ __launch_bounds__(128, 2) void gemm_lnh1_kernel(
    LNIn in, Ptrs3 W, Ptrs3 Bi, float* __restrict__ h3out)
{
    constexpr int K = CCH, M = HID;
    constexpr int AST = 68;
    extern __shared__ __align__(16) u32 dsm[];
    float* tile = reinterpret_cast<float*>(dsm);          // [128][128] fp32
    u32*   sB   = dsm;                                     // B image (reuse)
    u32*   sAf  = dsm + 16384;                             // A fp16 [128][68]

    const int z = blockIdx.z;
    const float* gam  = in.g[z];
    const float* bet  = in.b[z];
    const float* Bw   = W.p[z];
    const float* bias = Bi.p[z];

    const int tid  = threadIdx.x;
    const int lane = tid & 31;
    const int w    = tid >> 5;
    const int m0 = blockIdx.x * 64;
    const int n0 = blockIdx.y * 128;
    const int bI = n0 >> 12;
    const int s0 = n0 & (SEQ - 1);
    const float* Xb = in.x[z] + (size_t)bI * CCH * SEQ + s0;
    const int g  = lane >> 3;
    const int lr = lane & 7;

    // prefetch full B to registers (K=128: 16 f4 / thread)
    float4 bpre[16];
    #pragma unroll
    for (int it = 0; it < 16; it++) {
        int idx  = tid + it * 128;
        int krow = idx >> 4;
        int bcol = idx & 15;
        bpre[it] = *reinterpret_cast<const float4*>(&Bw[(size_t)krow * M + m0 + bcol * 4]);
    }

    // load raw A tile [chan][token] (coalesced along s)
    #pragma unroll
    for (int it = 0; it < 32; it++) {
        int idx = tid + it * 128;
        int c = idx >> 5, qd = idx & 31;
        float4 v = *reinterpret_cast<const float4*>(Xb + (size_t)c * SEQ + qd * 4);
        *reinterpret_cast<float4*>(&tile[c * 128 + qd * 4]) = v;
    }
    __syncthreads();

    // LN stats for token 'tid'
    float sum = 0.f, sq = 0.f;
    #pragma unroll 8
    for (int c = 0; c < CCH; c++) {
        float v = tile[c * 128 + tid];
        sum += v; sq += v * v;
    }
    float mu   = sum * (1.0f / CCH);
    float rstd = rsqrtf(sq * (1.0f / CCH) - mu * mu + 1e-5f);

    #pragma unroll 8
    for (int cp = 0; cp < 64; cp++) {
        float v0 = (tile[(2 * cp) * 128 + tid]     - mu) * rstd * __ldg(gam + 2 * cp)     + __ldg(bet + 2 * cp);
        float v1 = (tile[(2 * cp + 1) * 128 + tid] - mu) * rstd * __ldg(gam + 2 * cp + 1) + __ldg(bet + 2 * cp + 1);
        sAf[tid * AST + cp] = packhf(v0, v1);
    }
    __syncthreads();   // tile reads done; safe to overwrite with B

    #pragma unroll
    for (int it = 0; it < 16; it++) {
        int idx  = tid + it * 128;
        int krow = idx >> 4;
        int bcol = idx & 15;
        int o = (krow >> 4) * 576 + (krow & 15) * 36 + bcol * 2;
        sB[o]     = packhf(bpre[it].x, bpre[it].y);
        sB[o + 1] = packhf(bpre[it].z, bpre[it].w);
    }
    __syncthreads();

    const u32 aS = sptr(sAf);
    const u32 bS = sptr(sB);
    u32 aBase[2];
    #pragma unroll
    for (int mi = 0; mi < 2; mi++)
        aBase[mi] = aS + (u32)((w * 32 + mi * 16 + (g & 1) * 8 + lr) * (AST * 4) + (g >> 1) * 16);
    const u32 bBase = bS + (u32)((8 * (g & 1) + lr) * 144);

    float c[2][8][4];
    #pragma unroll
    for (int mi = 0; mi < 2; mi++)
        #pragma unroll
        for (int nt = 0; nt < 8; nt++)
            #pragma unroll
            for (int e = 0; e < 4; e++) c[mi][nt][e] = 0.f;

    #pragma unroll
    for (int t = 0; t < 8; t++) {
        u32 aF[2][4];
        #pragma unroll
        for (int mi = 0; mi < 2; mi++)
            ldsm4(aF[mi][0], aF[mi][1], aF[mi][2], aF[mi][3], aBase[mi] + t * 32);
        u32 bF[8][2];
        #pragma unroll
        for (int dp = 0; dp < 4; dp++)
            ldsm4t(bF[2 * dp][0], bF[2 * dp][1], bF[2 * dp + 1][0], bF[2 * dp + 1][1],
                   bBase + t * 2304 + (dp * 16 + 8 * (g >> 1)) * 2);
        #pragma unroll
        for (int mi = 0; mi < 2; mi++)
            #pragma unroll
            for (int nt = 0; nt < 8; nt++)
                mma16816h(c[mi][nt], aF[mi], bF[nt]);
    }

    float* C = h3out + (size_t)z * NTOK * HID;
    #pragma unroll
    for (int mi = 0; mi < 2; mi++) {
        int r0 = n0 + w * 32 + mi * 16 + (lane >> 2);
        #pragma unroll
        for (int nt = 0; nt < 8; nt++) {
            int col = m0 + nt * 8 + (lane & 3) * 2;
            float2 bb = *reinterpret_cast<const float2*>(&bias[col]);
            float v0 = c[mi][nt][0] + bb.x;
            float v1 = c[mi][nt][1] + bb.y;
            float v2 = c[mi][nt][2] + bb.x;
            float v3 = c[mi][nt][3] + bb.y;
            v0 = fmaxf(v0, 0.f) + 0.01f * fminf(v0, 0.f);
            v1 = fmaxf(v1, 0.f) + 0.01f * fminf(v1, 0.f);
            v2 = fmaxf(v2, 0.f) + 0.01f * fminf(v2, 0.f);
            v3 = fmaxf(v3, 0.f) + 0.01f * fminf(v3, 0.f);
            *reinterpret_cast<float2*>(&C[(size_t)r0 * HID + col])       = make_float2(v0, v1);
            *reinterpret_cast<float2*>(&C[(size_t)(r0 + 8) * HID + col]) = make_float2(v2, v3);
        }
    }
}

// ---------------- FA attention: unnormalized exp2 (from R12, passing) --------
#define KVT 64
#define ROWU 20

__global__ __launch_bounds__(256, 2) void attn_kernel(float* __restrict__ xo)
{
    __shared__ __align__(16) u32 skk[2][KVT * ROWU];
    __shared__ __align__(16) u32 svv[2][KVT * ROWU];

    const int tid  = threadIdx.x;
    const int lane = tid & 31;
    const int w    = tid >> 5;
    const int bh   = blockIdx.y;
    const int bb   = bh >> 2, h = bh & 3;
    const int sq0  = blockIdx.x * 128 + w * 16;

    u32 qR[2][4];
    {
        size_t qb = ((size_t)bh * SEQ + sq0 + (lane >> 2)) * 16;
        #pragma unroll
        for (int kt = 0; kt < 2; kt++) {
            int d0 = kt * 8 + (lane & 3);
            qR[kt][0] = g_qf[qb + d0];
            qR[kt][1] = g_qf[qb + 8 * 16 + d0];
            qR[kt][2] = g_qf[qb + d0 + 4];
            qR[kt][3] = g_qf[qb + 8 * 16 + d0 + 4];
        }
    }

    float o[4][4];
    #pragma unroll
    for (int dn = 0; dn < 4; dn++)
        #pragma unroll
        for (int e = 0; e < 4; e++) o[dn][e] = 0.f;
    float l0r = 0.f, l1r = 0.f;

    const int srow = tid >> 2;
    const int scq  = tid & 3;
    const size_t kvbase = (size_t)bh * SEQ * 16;

    const int g  = lane >> 3;
    const int lr = lane & 7;
    const u32 bK0 = sptr(&skk[0][0]);
    const u32 bV0 = sptr(&svv[0][0]);
    const u32 bufstride = KVT * ROWU * 4;
    const u32 ssoff = (u32)(srow * ROWU + scq * 4);

    u32 koff[2][4], voff[4][2];
    #pragma unroll
    for (int kt = 0; kt < 2; kt++)
        #pragma unroll
        for (int ap = 0; ap < 4; ap++)
            koff[kt][ap] = (u32)((16 * ap + 8 * (g >> 1) + lr) * 80 + (kt * 16 + 8 * (g & 1)) * 2);
    #pragma unroll
    for (int kt = 0; kt < 4; kt++)
        #pragma unroll
        for (int dp = 0; dp < 2; dp++)
            voff[kt][dp] = (u32)((16 * kt + 8 * (g & 1) + lr) * 80 + (dp * 16 + 8 * (g >> 1)) * 2);

    uint4 pk, pv;
    {
        size_t go = kvbase + (size_t)srow * 16 + scq * 4;
        pk = *reinterpret_cast<const uint4*>(g_kf + go);
        pv = *reinterpret_cast<const uint4*>(g_vf + go);
    }
    *reinterpret_cast<uint4*>(&skk[0][ssoff]) = pk;
    *reinterpret_cast<uint4*>(&svv[0][ssoff]) = pv;
    __syncthreads();

    const int NT = SEQ / KVT;
    for (int t = 0; t < NT; t++) {
        const int buf = t & 1;
        const u32 bK = bK0 + buf * bufstride;
        const u32 bV = bV0 + buf * bufstride;

        if (t + 1 < NT) {
            size_t go = kvbase + (size_t)((t + 1) * KVT + srow) * 16 + scq * 4;
            pk = *reinterpret_cast<const uint4*>(g_kf + go);
            pv = *reinterpret_cast<const uint4*>(g_vf + go);
        }

        float s[8][4];
        #pragma unroll
        for (int nt = 0; nt < 8; nt++)
            #pragma unroll
            for (int e = 0; e < 4; e++) s[nt][e] = 0.f;

        #pragma unroll
        for (int kt = 0; kt < 2; kt++) {
            u32 bk_[8][2];
            #pragma unroll
            for (int ap = 0; ap < 4; ap++)
                ldsm4(bk_[2 * ap][0], bk_[2 * ap][1], bk_[2 * ap + 1][0], bk_[2 * ap + 1][1],
                      bK + koff[kt][ap]);
            #pragma unroll
            for (int nt = 0; nt < 8; nt++)
                mma16816h(s[nt], qR[kt], bk_[nt]);
        }

        #pragma unroll
        for (int nt = 0; nt < 8; nt++) {
            float p0 = exf(s[nt][0]);
            float p1 = exf(s[nt][1]);
            float p2 = exf(s[nt][2]);
            float p3 = exf(s[nt][3]);
            s[nt][0] = p0; s[nt][1] = p1;
            s[nt][2] = p2; s[nt][3] = p3;
            l0r += p0 + p1;
            l1r += p2 + p3;
        }

        #pragma unroll
        for (int kt = 0; kt < 4; kt++) {
            u32 bv[4][2];
            #pragma unroll
            for (int dp = 0; dp < 2; dp++)
                ldsm4t(bv[2 * dp][0], bv[2 * dp][1], bv[2 * dp + 1][0], bv[2 * dp + 1][1],
                       bV + voff[kt][dp]);
            u32 pa[4];
            pa[0] = packhf(s[2 * kt][0],     s[2 * kt][1]);
            pa[1] = packhf(s[2 * kt][2],     s[2 * kt][3]);
            pa[2] = packhf(s[2 * kt + 1][0], s[2 * kt + 1][1]);
            pa[3] = packhf(s[2 * kt + 1][2], s[2 * kt + 1][3]);
            #pragma unroll
            for (int dn = 0; dn < 4; dn++)
                mma16816h(o[dn], pa, bv[dn]);
        }

        if (t + 1 < NT) {
            const int nb = (t + 1) & 1;
            *reinterpret_cast<uint4*>(&skk[nb][ssoff]) = pk;
            *reinterpret_cast<uint4*>(&svv[nb][ssoff]) = pv;
        }
        __syncthreads();
    }

    {
        l0r += __shfl_xor_sync(0xffffffffu, l0r, 1);
        l0r += __shfl_xor_sync(0xffffffffu, l0r, 2);
        l1r += __shfl_xor_sync(0xffffffffu, l1r, 1);
        l1r += __shfl_xor_sync(0xffffffffu, l1r, 2);
        float inv0 = 1.0f / l0r;
        float inv1 = 1.0f / l1r;
        int r = bb * SEQ + sq0 + (lane >> 2);
        #pragma unroll
        for (int dn = 0; dn < 4; dn++) {
            int cc = h * HD + dn * 8 + 2 * (lane & 3);
            float2 o0 = {o[dn][0] * inv0, o[dn][1] * inv0};
            float2 o1 = {o[dn][2] * inv1, o[dn][3] * inv1};
            *reinterpret_cast<float2*>(xo + (size_t)r * CCH + cc)       = o0;
            *reinterpret_cast<float2*>(xo + (size_t)(r + 8) * CCH + cc) = o1;
        }
    }
}

// ---------------- launch ----------------------------------------------------
static float* symf(const void* symbol) {
    void* p = nullptr;
    cudaGetSymbolAddress(&p, symbol);
    return reinterpret_cast<float*>(p);
}
static u32* symu(const void* symbol) {
    void* p = nullptr;
    cudaGetSymbolAddress(&p, symbol);
    return reinterpret_cast<u32*>(p);
}

extern "C" void kernel_launch(void* const* d_in, const int* in_sizes, int n_in,
                              void* d_out, int out_size)
{
    const float* q = (const float*)d_in[0];
    const float* k = (const float*)d_in[1];
    const float* v = (const float*)d_in[2];
    const float* ln_g[3]  = {(const float*)d_in[3],  (const float*)d_in[9],  (const float*)d_in[15]};
    const float* ln_b[3]  = {(const float*)d_in[4],  (const float*)d_in[10], (const float*)d_in[16]};
    const float* w1[3]    = {(const float*)d_in[5],  (const float*)d_in[11], (const float*)d_in[17]};
    const float* b1[3]    = {(const float*)d_in[6],  (const float*)d_in[12], (const float*)d_in[18]};
    const float* w2[3]    = {(const float*)d_in[7],  (const float*)d_in[13], (const float*)d_in[19]};
    const float* b2[3]    = {(const float*)d_in[8],  (const float*)d_in[14], (const float*)d_in[20]};
    const float* m1_w1 = (const float*)d_in[21];
    const float* m1_b1 = (const float*)d_in[22];
    const float* m1_w2 = (const float*)d_in[23];
    const float* m1_b2 = (const float*)d_in[24];
    const float* m2_w1 = (const float*)d_in[25];
    const float* m2_b1 = (const float*)d_in[26];
    const float* m2_w2 = (const float*)d_in[27];
    const float* m2_b2 = (const float*)d_in[28];

    float* vp  = symf(g_vp);
    float* x   = symf(g_x);
    float* rs1 = symf(g_rs1);
    float* hb  = symf(g_h);
    float* h3  = symf(g_h3);
    u32* qf = symu(g_qf);
    u32* kf = symu(g_kf);
    u32* vf = symu(g_vf);

    const float qsc = 1.44269504088896f / 5.65685424949238f;  // log2e/sqrt(32)

    // dynamic smem sizes
    const int SM128 = (128 * 68 + 8 * 576) * 4;     // 53248
    const int SM256 = (128 * 132 + 16 * 576) * 4;   // 104448

    cudaFuncSetAttribute(gemm_lnh1_kernel,
                         cudaFuncAttributeMaxDynamicSharedMemorySize, LN_SMEM);
    cudaFuncSetAttribute(gemm_rqkv,
                         cudaFuncAttributeMaxDynamicSharedMemorySize, SM256);
    cudaFuncSetAttribute(gemm_rk<128, true,  false, false>,
                         cudaFuncAttributeMaxDynamicSharedMemorySize, SM128);
    cudaFuncSetAttribute(gemm_rk<256, false, true,  false>,
                         cudaFuncAttributeMaxDynamicSharedMemorySize, SM256);
    cudaFuncSetAttribute(gemm_rk<256, false, true,  true>,
                         cudaFuncAttributeMaxDynamicSharedMemorySize, SM256);

    // ---- fused LN + GEMM1 (raw input -> h3), batched over q/k/v ----
    LNIn lp;
    lp.x[0] = q; lp.x[1] = k; lp.x[2] = v;
    for (int i = 0; i < 3; i++) { lp.g[i] = ln_g[i]; lp.b[i] = ln_b[i]; }
    Ptrs3 W1 = {{w1[0], w1[1], w1[2]}};
    Ptrs3 B1 = {{b1[0], b1[1], b1[2]}};
    gemm_lnh1_kernel<<<dim3(HID / 64, NTOK / 128, 3), 128, LN_SMEM>>>(lp, W1, B1, h3);

    // ---- batched GEMM2 (2C->C, fp16 head-major out; v also fp32) ----
    Ptrs3 W2 = {{w2[0], w2[1], w2[2]}};
    Ptrs3 B2 = {{b2[0], b2[1], b2[2]}};
    QKVOut qo = {{qf, kf, vf}, {qsc, 1.f, 1.f}, vp};
    gemm_rqkv<<<dim3(CCH / 64, NTOK / 128, 3), 128, SM256>>>(h3, (long)NTOK * HID, W2, B2, qo);

    // ---- attention ----
    attn_kernel<<<dim3(SEQ / 128, 2 * NH), 256>>>(x);

    // ---- MLPs (resident fp16); last GEMM writes [B,C,S] directly ----
    dim3 g1(HID / 64, NTOK / 128);
    dim3 g2(CCH / 64, NTOK / 128);
    gemm_rk<128, true,  false, false><<<g1, 128, SM128>>>(x,   m1_w1, m1_b1, nullptr, hb,  HID);
    gemm_rk<256, false, true,  false><<<g2, 128, SM256>>>(hb,  m1_w2, m1_b2, vp,      rs1, CCH);
    gemm_rk<128, true,  false, false><<<g1, 128, SM128>>>(rs1, m2_w1, m2_b1, nullptr, hb,  HID);
    gemm_rk<256, false, true,  true ><<<g2, 128, SM256>>>(hb,  m2_w2, m2_b2, rs1, (float*)d_out, CCH);
}

// round 15
// speedup vs baseline: 1.0114x; 1.0114x over previous
#include <cuda_runtime.h>
#include <cuda_bf16.h>
#include <cstdint>

#define NTOK 8192      // B*S
#define CCH  128       // C
#define HID  256       // 2C
#define SEQ  4096      // S per batch
#define NH   4
#define HD   32

typedef unsigned int u32;

// ---------------- scratch (static device memory, no allocs) ----------------
__device__ float g_vp [NTOK * CCH];
__device__ float g_x  [NTOK * CCH];
__device__ float g_rs1[NTOK * CCH];
__device__ float g_h  [NTOK * HID];
__device__ float g_h3 [3 * NTOK * HID];
// head-major fp16 operands: [b*NH+h][token][16 u32]
__device__ u32 g_qf[2 * NH * SEQ * 16];
__device__ u32 g_kf[2 * NH * SEQ * 16];
__device__ u32 g_vf[2 * NH * SEQ * 16];

struct Ptrs3  { const float* p[3]; };
struct LNIn   { const float* x[3]; const float* g[3]; const float* b[3]; };
struct QKVOut { u32* o16[3]; float sc[3]; float* vC; };

// ---------------- helpers -----------------------------------------------------
__device__ __forceinline__ u32 packhf(float x, float y) {      // fp16x2, x->low
    u32 d; asm("cvt.rn.f16x2.f32 %0,%2,%1;" : "=r"(d) : "f"(x), "f"(y)); return d;
}
__device__ __forceinline__ float exf(float x) {                // MUFU exp2
    float r; asm("ex2.approx.f32 %0,%1;" : "=f"(r) : "f"(x)); return r;
}
__device__ __forceinline__ u32 sptr(const void* p) {
    u32 a; asm("{.reg .u64 t; cvta.to.shared.u64 t,%1; cvt.u32.u64 %0,t;}" : "=r"(a) : "l"(p));
    return a;
}
__device__ __forceinline__ void mma16816h(float* c, const u32* a, const u32* b) {
    asm volatile(
        "mma.sync.aligned.m16n8k16.row.col.f32.f16.f16.f32 "
        "{%0,%1,%2,%3},{%4,%5,%6,%7},{%8,%9},{%0,%1,%2,%3};"
        : "+f"(c[0]), "+f"(c[1]), "+f"(c[2]), "+f"(c[3])
        : "r"(a[0]), "r"(a[1]), "r"(a[2]), "r"(a[3]), "r"(b[0]), "r"(b[1]));
}
__device__ __forceinline__ void ldsm4(u32& r0, u32& r1, u32& r2, u32& r3, u32 addr) {
    asm volatile("ldmatrix.sync.aligned.m8n8.x4.shared.b16 {%0,%1,%2,%3},[%4];"
                 : "=r"(r0), "=r"(r1), "=r"(r2), "=r"(r3) : "r"(addr));
}
__device__ __forceinline__ void ldsm4t(u32& r0, u32& r1, u32& r2, u32& r3, u32 addr) {
    asm volatile("ldmatrix.sync.aligned.m8n8.x4.trans.shared.b16 {%0,%1,%2,%3},[%4];"
                 : "=r"(r0), "=r"(r1), "=r"(r2), "=r"(r3) : "r"(addr));
}

// ==================== resident fp16 GEMM, 64x64 tiles =========================
// A image: 64 rows x (K/2+4) u32 rows. B image: K/16 tiles of [16][36] u32.
template <int K, bool LEAKY, bool RES, bool TRANS>
__global__ __launch_bounds__(128, (K == 128) ? 4 : 3) void gemm_rk(
    const float* __restrict__ A, const float* __restrict__ Bw,
    const float* __restrict__ bias, const float* __restrict__ res,
    float* __restrict__ C, int M)
{
    constexpr int AST = K / 2 + 4;
    constexpr int NKT = K / 16;
    extern __shared__ __align__(16) u32 dsm[];
    u32* sAf = dsm;                       // 64*AST u32
    u32* sB  = dsm + 64 * AST;            // NKT*576 u32

    const int tid  = threadIdx.x;
    const int lane = tid & 31;
    const int w    = tid >> 5;
    const int n0 = blockIdx.y * 64;
    const int m0 = blockIdx.x * 64;
    const int g  = lane >> 3;
    const int lr = lane & 7;

    // ---- stage A (64 rows x K) ------------------------------------------------
    #pragma unroll 8
    for (int it = 0; it < K / 8; it++) {
        int idx  = tid + it * 128;
        int row  = idx / (K / 4);
        int colq = idx % (K / 4);
        float4 f = *reinterpret_cast<const float4*>(&A[(size_t)(n0 + row) * K + colq * 4]);
        sAf[row * AST + colq * 2]     = packhf(f.x, f.y);
        sAf[row * AST + colq * 2 + 1] = packhf(f.z, f.w);
    }
    // ---- stage B (K x 64) -------------------------------------------------------
    #pragma unroll 8
    for (int it = 0; it < K / 8; it++) {
        int idx  = tid + it * 128;
        int krow = idx >> 4;
        int bcol = idx & 15;
        float4 f = *reinterpret_cast<const float4*>(&Bw[(size_t)krow * M + m0 + bcol * 4]);
        int o = (krow >> 4) * 576 + (krow & 15) * 36 + bcol * 2;
        sB[o]     = packhf(f.x, f.y);
        sB[o + 1] = packhf(f.z, f.w);
    }
    __syncthreads();

    // ---- compute (no barriers) --------------------------------------------------
    const u32 aS = sptr(sAf);
    const u32 bS = sptr(sB);
    const u32 aBase = aS + (u32)((w * 16 + (g & 1) * 8 + lr) * (AST * 4) + (g >> 1) * 16);
    const u32 bBase = bS + (u32)((8 * (g & 1) + lr) * 144);

    float c[8][4];
    #pragma unroll
    for (int nt = 0; nt < 8; nt++)
        #pragma unroll
        for (int e = 0; e < 4; e++) c[nt][e] = 0.f;

    #pragma unroll
    for (int t = 0; t < NKT; t++) {
        u32 aF[4];
        ldsm4(aF[0], aF[1], aF[2], aF[3], aBase + t * 32);
        u32 bF[8][2];
        #pragma unroll
        for (int dp = 0; dp < 4; dp++)
            ldsm4t(bF[2 * dp][0], bF[2 * dp][1], bF[2 * dp + 1][0], bF[2 * dp + 1][1],
                   bBase + t * 2304 + (dp * 16 + 8 * (g >> 1)) * 2);
        #pragma unroll
        for (int nt = 0; nt < 8; nt++)
            mma16816h(c[nt], aF, bF[nt]);
    }

    // ---- epilogue ------------------------------------------------------------------
    int r0 = n0 + w * 16 + (lane >> 2);
    #pragma unroll
    for (int nt = 0; nt < 8; nt++) {
        int col = m0 + nt * 8 + (lane & 3) * 2;
        float2 bb = *reinterpret_cast<const float2*>(&bias[col]);
        float v0 = c[nt][0] + bb.x;
        float v1 = c[nt][1] + bb.y;
        float v2 = c[nt][2] + bb.x;
        float v3 = c[nt][3] + bb.y;
        if (LEAKY) {
            v0 = fmaxf(v0, 0.f) + 0.01f * fminf(v0, 0.f);
            v1 = fmaxf(v1, 0.f) + 0.01f * fminf(v1, 0.f);
            v2 = fmaxf(v2, 0.f) + 0.01f * fminf(v2, 0.f);
            v3 = fmaxf(v3, 0.f) + 0.01f * fminf(v3, 0.f);
        }
        if (RES) {
            float2 r4a = *reinterpret_cast<const float2*>(&res[(size_t)r0 * M + col]);
            float2 r4b = *reinterpret_cast<const float2*>(&res[(size_t)(r0 + 8) * M + col]);
            v0 += r4a.x; v1 += r4a.y; v2 += r4b.x; v3 += r4b.y;
        }
        if (!TRANS) {
            *reinterpret_cast<float2*>(&C[(size_t)r0 * M + col])       = make_float2(v0, v1);
            *reinterpret_cast<float2*>(&C[(size_t)(r0 + 8) * M + col]) = make_float2(v2, v3);
        } else {
            int bI = r0 >> 12, sI = r0 & (SEQ - 1);
            float* dst = C + (size_t)bI * CCH * SEQ + sI;
            dst[(size_t)col * SEQ]           = v0;
            dst[(size_t)(col + 1) * SEQ]     = v1;
            dst[(size_t)col * SEQ + 8]       = v2;
            dst[(size_t)(col + 1) * SEQ + 8] = v3;
        }
    }
}

// ==================== resident qkv GEMM2 (K=256, batched z) ===================
__global__ __launch_bounds__(128, 2) void gemm_rqkv(
    const float* __restrict__ Abase, long Astride,
    Ptrs3 W, Ptrs3 Bi, QKVOut qo)
{
    constexpr int K = HID, M = CCH;
    constexpr int AST = K / 2 + 4;       // 132
    constexpr int NKT = K / 16;          // 16
    extern __shared__ __align__(16) u32 dsm[];
    u32* sAf = dsm;
    u32* sB  = dsm + 128 * AST;

    const int z = blockIdx.z;
    const float* A    = Abase + (size_t)z * Astride;
    const float* Bw   = W.p[z];
    const float* bias = Bi.p[z];

    const int tid  = threadIdx.x;
    const int lane = tid & 31;
    const int w    = tid >> 5;
    const int n0 = blockIdx.y * 128;
    const int m0 = blockIdx.x * 64;
    const int g  = lane >> 3;
    const int lr = lane & 7;

    #pragma unroll 8
    for (int it = 0; it < K / 4; it++) {
        int idx  = tid + it * 128;
        int row  = idx / (K / 4);
        int colq = idx % (K / 4);
        float4 f = *reinterpret_cast<const float4*>(&A[(size_t)(n0 + row) * K + colq * 4]);
        sAf[row * AST + colq * 2]     = packhf(f.x, f.y);
        sAf[row * AST + colq * 2 + 1] = packhf(f.z, f.w);
    }
    #pragma unroll 8
    for (int it = 0; it < K / 8; it++) {
        int idx  = tid + it * 128;
        int krow = idx >> 4;
        int bcol = idx & 15;
        float4 f = *reinterpret_cast<const float4*>(&Bw[(size_t)krow * M + m0 + bcol * 4]);
        int o = (krow >> 4) * 576 + (krow & 15) * 36 + bcol * 2;
        sB[o]     = packhf(f.x, f.y);
        sB[o + 1] = packhf(f.z, f.w);
    }
    __syncthreads();

    const u32 aS = sptr(sAf);
    const u32 bS = sptr(sB);
    u32 aBase[2];
    #pragma unroll
    for (int mi = 0; mi < 2; mi++)
        aBase[mi] = aS + (u32)((w * 32 + mi * 16 + (g & 1) * 8 + lr) * (AST * 4) + (g >> 1) * 16);
    const u32 bBase = bS + (u32)((8 * (g & 1) + lr) * 144);

    float c[2][8][4];
    #pragma unroll
    for (int mi = 0; mi < 2; mi++)
        #pragma unroll
        for (int nt = 0; nt < 8; nt++)
            #pragma unroll
            for (int e = 0; e < 4; e++) c[mi][nt][e] = 0.f;

    #pragma unroll
    for (int t = 0; t < NKT; t++) {
        u32 aF[2][4];
        #pragma unroll
        for (int mi = 0; mi < 2; mi++)
            ldsm4(aF[mi][0], aF[mi][1], aF[mi][2], aF[mi][3], aBase[mi] + t * 32);
        u32 bF[8][2];
        #pragma unroll
        for (int dp = 0; dp < 4; dp++)
            ldsm4t(bF[2 * dp][0], bF[2 * dp][1], bF[2 * dp + 1][0], bF[2 * dp + 1][1],
                   bBase + t * 2304 + (dp * 16 + 8 * (g >> 1)) * 2);
        #pragma unroll
        for (int mi = 0; mi < 2; mi++)
            #pragma unroll
            for (int nt = 0; nt < 8; nt++)
                mma16816h(c[mi][nt], aF[mi], bF[nt]);
    }

    #pragma unroll
    for (int mi = 0; mi < 2; mi++) {
        int r0 = n0 + w * 32 + mi * 16 + (lane >> 2);
        #pragma unroll
        for (int nt = 0; nt < 8; nt++) {
            int col = m0 + nt * 8 + (lane & 3) * 2;
            float2 bb = *reinterpret_cast<const float2*>(&bias[col]);
            float v0 = c[mi][nt][0] + bb.x;
            float v1 = c[mi][nt][1] + bb.y;
            float v2 = c[mi][nt][2] + bb.x;
            float v3 = c[mi][nt][3] + bb.y;
            int h = col >> 5, dpair = (col & 31) >> 1;
            int bI = r0 >> 12, sI = r0 & (SEQ - 1);
            size_t oA = ((size_t)(bI * NH + h) * SEQ + sI) * 16 + dpair;
            size_t oB = oA + 8 * 16;
            u32* o16 = qo.o16[z];
            float sc = qo.sc[z];
            o16[oA] = packhf(v0 * sc, v1 * sc);
            o16[oB] = packhf(v2 * sc, v3 * sc);
            if (z == 2) {
                *reinterpret_cast<float2*>(&qo.vC[(size_t)r0 * M + col])       = make_float2(v0, v1);
                *reinterpret_cast<float2*>(&qo.vC[(size_t)(r0 + 8) * M + col]) = make_float2(v2, v3);
            }
        }
    }
}

// ==================== fused LN + GEMM1 (resident B) ===========================
#define LN_SMEM (65536 + 34816)

__global__ __launch_bounds__(128, 2) void gemm_lnh1_kernel(
    LNIn in, Ptrs3 W, Ptrs3 Bi, float* __restrict__ h3out)
{
    constexpr int K = CCH, M = HID;
    constexpr int AST = 68;
    extern __shared__ __align__(16) u32 dsm[];
    float* tile = reinterpret_cast<float*>(dsm);          // [128][128] fp32
    u32*   sB   = dsm;                                     // B image (reuse)
    u32*   sAf  = dsm + 16384;                             // A fp16 [128][68]

    const int z = blockIdx.z;
    const float* gam  = in.g[z];
    const float* bet  = in.b[z];
    const float* Bw   = W.p[z];
    const float* bias = Bi.p[z];

    const int tid  = threadIdx.x;
    const int lane = tid & 31;
    const int w    = tid >> 5;
    const int m0 = blockIdx.x * 64;
    const int n0 = blockIdx.y * 128;
    const int bI = n0 >> 12;
    const int s0 = n0 & (SEQ - 1);
    const float* Xb = in.x[z] + (size_t)bI * CCH * SEQ + s0;
    const int g  = lane >> 3;
    const int lr = lane & 7;

    float4 bpre[16];
    #pragma unroll
    for (int it = 0; it < 16; it++) {
        int idx  = tid + it * 128;
        int krow = idx >> 4;
        int bcol = idx & 15;
        bpre[it] = *reinterpret_cast<const float4*>(&Bw[(size_t)krow * M + m0 + bcol * 4]);
    }

    #pragma unroll
    for (int it = 0; it < 32; it++) {
        int idx = tid + it * 128;
        int c = idx >> 5, qd = idx & 31;
        float4 v = *reinterpret_cast<const float4*>(Xb + (size_t)c * SEQ + qd * 4);
        *reinterpret_cast<float4*>(&tile[c * 128 + qd * 4]) = v;
    }
    __syncthreads();

    float sum = 0.f, sq = 0.f;
    #pragma unroll 8
    for (int c = 0; c < CCH; c++) {
        float v = tile[c * 128 + tid];
        sum += v; sq += v * v;
    }
    float mu   = sum * (1.0f / CCH);
    float rstd = rsqrtf(sq * (1.0f / CCH) - mu * mu + 1e-5f);

    #pragma unroll 8
    for (int cp = 0; cp < 64; cp++) {
        float v0 = (tile[(2 * cp) * 128 + tid]     - mu) * rstd * __ldg(gam + 2 * cp)     + __ldg(bet + 2 * cp);
        float v1 = (tile[(2 * cp + 1) * 128 + tid] - mu) * rstd * __ldg(gam + 2 * cp + 1) + __ldg(bet + 2 * cp + 1);
        sAf[tid * AST + cp] = packhf(v0, v1);
    }
    __syncthreads();

    #pragma unroll
    for (int it = 0; it < 16; it++) {
        int idx  = tid + it * 128;
        int krow = idx >> 4;
        int bcol = idx & 15;
        int o = (krow >> 4) * 576 + (krow & 15) * 36 + bcol * 2;
        sB[o]     = packhf(bpre[it].x, bpre[it].y);
        sB[o + 1] = packhf(bpre[it].z, bpre[it].w);
    }
    __syncthreads();

    const u32 aS = sptr(sAf);
    const u32 bS = sptr(sB);
    u32 aBase[2];
    #pragma unroll
    for (int mi = 0; mi < 2; mi++)
        aBase[mi] = aS + (u32)((w * 32 + mi * 16 + (g & 1) * 8 + lr) * (AST * 4) + (g >> 1) * 16);
    const u32 bBase = bS + (u32)((8 * (g & 1) + lr) * 144);

    float c[2][8][4];
    #pragma unroll
    for (int mi = 0; mi < 2; mi++)
        #pragma unroll
        for (int nt = 0; nt < 8; nt++)
            #pragma unroll
            for (int e = 0; e < 4; e++) c[mi][nt][e] = 0.f;

    #pragma unroll
    for (int t = 0; t < 8; t++) {
        u32 aF[2][4];
        #pragma unroll
        for (int mi = 0; mi < 2; mi++)
            ldsm4(aF[mi][0], aF[mi][1], aF[mi][2], aF[mi][3], aBase[mi] + t * 32);
        u32 bF[8][2];
        #pragma unroll
        for (int dp = 0; dp < 4; dp++)
            ldsm4t(bF[2 * dp][0], bF[2 * dp][1], bF[2 * dp + 1][0], bF[2 * dp + 1][1],
                   bBase + t * 2304 + (dp * 16 + 8 * (g >> 1)) * 2);
        #pragma unroll
        for (int mi = 0; mi < 2; mi++)
            #pragma unroll
            for (int nt = 0; nt < 8; nt++)
                mma16816h(c[mi][nt], aF[mi], bF[nt]);
    }

    float* C = h3out + (size_t)z * NTOK * HID;
    #pragma unroll
    for (int mi = 0; mi < 2; mi++) {
        int r0 = n0 + w * 32 + mi * 16 + (lane >> 2);
        #pragma unroll
        for (int nt = 0; nt < 8; nt++) {
            int col = m0 + nt * 8 + (lane & 3) * 2;
            float2 bb = *reinterpret_cast<const float2*>(&bias[col]);
            float v0 = c[mi][nt][0] + bb.x;
            float v1 = c[mi][nt][1] + bb.y;
            float v2 = c[mi][nt][2] + bb.x;
            float v3 = c[mi][nt][3] + bb.y;
            v0 = fmaxf(v0, 0.f) + 0.01f * fminf(v0, 0.f);
            v1 = fmaxf(v1, 0.f) + 0.01f * fminf(v1, 0.f);
            v2 = fmaxf(v2, 0.f) + 0.01f * fminf(v2, 0.f);
            v3 = fmaxf(v3, 0.f) + 0.01f * fminf(v3, 0.f);
            *reinterpret_cast<float2*>(&C[(size_t)r0 * HID + col])       = make_float2(v0, v1);
            *reinterpret_cast<float2*>(&C[(size_t)(r0 + 8) * HID + col]) = make_float2(v2, v3);
        }
    }
}

// ---------------- FA attention: unnormalized exp2 (passing) ------------------
#define KVT 64
#define ROWU 20

__global__ __launch_bounds__(256, 2) void attn_kernel(float* __restrict__ xo)
{
    __shared__ __align__(16) u32 skk[2][KVT * ROWU];
    __shared__ __align__(16) u32 svv[2][KVT * ROWU];

    const int tid  = threadIdx.x;
    const int lane = tid & 31;
    const int w    = tid >> 5;
    const int bh   = blockIdx.y;
    const int bb   = bh >> 2, h = bh & 3;
    const int sq0  = blockIdx.x * 128 + w * 16;

    u32 qR[2][4];
    {
        size_t qb = ((size_t)bh * SEQ + sq0 + (lane >> 2)) * 16;
        #pragma unroll
        for (int kt = 0; kt < 2; kt++) {
            int d0 = kt * 8 + (lane & 3);
            qR[kt][0] = g_qf[qb + d0];
            qR[kt][1] = g_qf[qb + 8 * 16 + d0];
            qR[kt][2] = g_qf[qb + d0 + 4];
            qR[kt][3] = g_qf[qb + 8 * 16 + d0 + 4];
        }
    }

    float o[4][4];
    #pragma unroll
    for (int dn = 0; dn < 4; dn++)
        #pragma unroll
        for (int e = 0; e < 4; e++) o[dn][e] = 0.f;
    float l0r = 0.f, l1r = 0.f;

    const int srow = tid >> 2;
    const int scq  = tid & 3;
    const size_t kvbase = (size_t)bh * SEQ * 16;

    const int g  = lane >> 3;
    const int lr = lane & 7;
    const u32 bK0 = sptr(&skk[0][0]);
    const u32 bV0 = sptr(&svv[0][0]);
    const u32 bufstride = KVT * ROWU * 4;
    const u32 ssoff = (u32)(srow * ROWU + scq * 4);

    u32 koff[2][4], voff[4][2];
    #pragma unroll
    for (int kt = 0; kt < 2; kt++)
        #pragma unroll
        for (int ap = 0; ap < 4; ap++)
            koff[kt][ap] = (u32)((16 * ap + 8 * (g >> 1) + lr) * 80 + (kt * 16 + 8 * (g & 1)) * 2);
    #pragma unroll
    for (int kt = 0; kt < 4; kt++)
        #pragma unroll
        for (int dp = 0; dp < 2; dp++)
            voff[kt][dp] = (u32)((16 * kt + 8 * (g & 1) + lr) * 80 + (dp * 16 + 8 * (g >> 1)) * 2);

    uint4 pk, pv;
    {
        size_t go = kvbase + (size_t)srow * 16 + scq * 4;
        pk = *reinterpret_cast<const uint4*>(g_kf + go);
        pv = *reinterpret_cast<const uint4*>(g_vf + go);
    }
    *reinterpret_cast<uint4*>(&skk[0][ssoff]) = pk;
    *reinterpret_cast<uint4*>(&svv[0][ssoff]) = pv;
    __syncthreads();

    const int NT = SEQ / KVT;
    for (int t = 0; t < NT; t++) {
        const int buf = t & 1;
        const u32 bK = bK0 + buf * bufstride;
        const u32 bV = bV0 + buf * bufstride;

        if (t + 1 < NT) {
            size_t go = kvbase + (size_t)((t + 1) * KVT + srow) * 16 + scq * 4;
            pk = *reinterpret_cast<const uint4*>(g_kf + go);
            pv = *reinterpret_cast<const uint4*>(g_vf + go);
        }

        float s[8][4];
        #pragma unroll
        for (int nt = 0; nt < 8; nt++)
            #pragma unroll
            for (int e = 0; e < 4; e++) s[nt][e] = 0.f;

        #pragma unroll
        for (int kt = 0; kt < 2; kt++) {
            u32 bk_[8][2];
            #pragma unroll
            for (int ap = 0; ap < 4; ap++)
                ldsm4(bk_[2 * ap][0], bk_[2 * ap][1], bk_[2 * ap + 1][0], bk_[2 * ap + 1][1],
                      bK + koff[kt][ap]);
            #pragma unroll
            for (int nt = 0; nt < 8; nt++)
                mma16816h(s[nt], qR[kt], bk_[nt]);
        }

        #pragma unroll
        for (int nt = 0; nt < 8; nt++) {
            float p0 = exf(s[nt][0]);
            float p1 = exf(s[nt][1]);
            float p2 = exf(s[nt][2]);
            float p3 = exf(s[nt][3]);
            s[nt][0] = p0; s[nt][1] = p1;
            s[nt][2] = p2; s[nt][3] = p3;
            l0r += p0 + p1;
            l1r += p2 + p3;
        }

        #pragma unroll
        for (int kt = 0; kt < 4; kt++) {
            u32 bv[4][2];
            #pragma unroll
            for (int dp = 0; dp < 2; dp++)
                ldsm4t(bv[2 * dp][0], bv[2 * dp][1], bv[2 * dp + 1][0], bv[2 * dp + 1][1],
                       bV + voff[kt][dp]);
            u32 pa[4];
            pa[0] = packhf(s[2 * kt][0],     s[2 * kt][1]);
            pa[1] = packhf(s[2 * kt][2],     s[2 * kt][3]);
            pa[2] = packhf(s[2 * kt + 1][0], s[2 * kt + 1][1]);
            pa[3] = packhf(s[2 * kt + 1][2], s[2 * kt + 1][3]);
            #pragma unroll
            for (int dn = 0; dn < 4; dn++)
                mma16816h(o[dn], pa, bv[dn]);
        }

        if (t + 1 < NT) {
            const int nb = (t + 1) & 1;
            *reinterpret_cast<uint4*>(&skk[nb][ssoff]) = pk;
            *reinterpret_cast<uint4*>(&svv[nb][ssoff]) = pv;
        }
        __syncthreads();
    }

    {
        l0r += __shfl_xor_sync(0xffffffffu, l0r, 1);
        l0r += __shfl_xor_sync(0xffffffffu, l0r, 2);
        l1r += __shfl_xor_sync(0xffffffffu, l1r, 1);
        l1r += __shfl_xor_sync(0xffffffffu, l1r, 2);
        float inv0 = 1.0f / l0r;
        float inv1 = 1.0f / l1r;
        int r = bb * SEQ + sq0 + (lane >> 2);
        #pragma unroll
        for (int dn = 0; dn < 4; dn++) {
            int cc = h * HD + dn * 8 + 2 * (lane & 3);
            float2 o0 = {o[dn][0] * inv0, o[dn][1] * inv0};
            float2 o1 = {o[dn][2] * inv1, o[dn][3] * inv1};
            *reinterpret_cast<float2*>(xo + (size_t)r * CCH + cc)       = o0;
            *reinterpret_cast<float2*>(xo + (size_t)(r + 8) * CCH + cc) = o1;
        }
    }
}

// ---------------- launch ----------------------------------------------------
static float* symf(const void* symbol) {
    void* p = nullptr;
    cudaGetSymbolAddress(&p, symbol);
    return reinterpret_cast<float*>(p);
}
static u32* symu(const void* symbol) {
    void* p = nullptr;
    cudaGetSymbolAddress(&p, symbol);
    return reinterpret_cast<u32*>(p);
}

extern "C" void kernel_launch(void* const* d_in, const int* in_sizes, int n_in,
                              void* d_out, int out_size)
{
    const float* q = (const float*)d_in[0];
    const float* k = (const float*)d_in[1];
    const float* v = (const float*)d_in[2];
    const float* ln_g[3]  = {(const float*)d_in[3],  (const float*)d_in[9],  (const float*)d_in[15]};
    const float* ln_b[3]  = {(const float*)d_in[4],  (const float*)d_in[10], (const float*)d_in[16]};
    const float* w1[3]    = {(const float*)d_in[5],  (const float*)d_in[11], (const float*)d_in[17]};
    const float* b1[3]    = {(const float*)d_in[6],  (const float*)d_in[12], (const float*)d_in[18]};
    const float* w2[3]    = {(const float*)d_in[7],  (const float*)d_in[13], (const float*)d_in[19]};
    const float* b2[3]    = {(const float*)d_in[8],  (const float*)d_in[14], (const float*)d_in[20]};
    const float* m1_w1 = (const float*)d_in[21];
    const float* m1_b1 = (const float*)d_in[22];
    const float* m1_w2 = (const float*)d_in[23];
    const float* m1_b2 = (const float*)d_in[24];
    const float* m2_w1 = (const float*)d_in[25];
    const float* m2_b1 = (const float*)d_in[26];
    const float* m2_w2 = (const float*)d_in[27];
    const float* m2_b2 = (const float*)d_in[28];

    float* vp  = symf(g_vp);
    float* x   = symf(g_x);
    float* rs1 = symf(g_rs1);
    float* hb  = symf(g_h);
    float* h3  = symf(g_h3);
    u32* qf = symu(g_qf);
    u32* kf = symu(g_kf);
    u32* vf = symu(g_vf);

    const float qsc = 1.44269504088896f / 5.65685424949238f;  // log2e/sqrt(32)

    // dynamic smem sizes (64-row tiles for MLP)
    const int SM128 = (64 * 68 + 8 * 576) * 4;      // 35840
    const int SM256 = (64 * 132 + 16 * 576) * 4;    // 70656
    const int SMQKV = (128 * 132 + 16 * 576) * 4;   // 104448

    cudaFuncSetAttribute(gemm_lnh1_kernel,
                         cudaFuncAttributeMaxDynamicSharedMemorySize, LN_SMEM);
    cudaFuncSetAttribute(gemm_rqkv,
                         cudaFuncAttributeMaxDynamicSharedMemorySize, SMQKV);
    cudaFuncSetAttribute(gemm_rk<128, true,  false, false>,
                         cudaFuncAttributeMaxDynamicSharedMemorySize, SM128);
    cudaFuncSetAttribute(gemm_rk<256, false, true,  false>,
                         cudaFuncAttributeMaxDynamicSharedMemorySize, SM256);
    cudaFuncSetAttribute(gemm_rk<256, false, true,  true>,
                         cudaFuncAttributeMaxDynamicSharedMemorySize, SM256);

    // ---- fused LN + GEMM1 (raw input -> h3), batched over q/k/v ----
    LNIn lp;
    lp.x[0] = q; lp.x[1] = k; lp.x[2] = v;
    for (int i = 0; i < 3; i++) { lp.g[i] = ln_g[i]; lp.b[i] = ln_b[i]; }
    Ptrs3 W1 = {{w1[0], w1[1], w1[2]}};
    Ptrs3 B1 = {{b1[0], b1[1], b1[2]}};
    gemm_lnh1_kernel<<<dim3(HID / 64, NTOK / 128, 3), 128, LN_SMEM>>>(lp, W1, B1, h3);

    // ---- batched GEMM2 (2C->C, fp16 head-major out; v also fp32) ----
    Ptrs3 W2 = {{w2[0], w2[1], w2[2]}};
    Ptrs3 B2 = {{b2[0], b2[1], b2[2]}};
    QKVOut qo = {{qf, kf, vf}, {qsc, 1.f, 1.f}, vp};
    gemm_rqkv<<<dim3(CCH / 64, NTOK / 128, 3), 128, SMQKV>>>(h3, (long)NTOK * HID, W2, B2, qo);

    // ---- attention ----
    attn_kernel<<<dim3(SEQ / 128, 2 * NH), 256>>>(x);

    // ---- MLPs (64x64 tiles, resident fp16); last writes [B,C,S] directly ----
    dim3 g1(HID / 64, NTOK / 64);   // (4, 128) = 512 CTAs
    dim3 g2(CCH / 64, NTOK / 64);   // (2, 128) = 256 CTAs
    gemm_rk<128, true,  false, false><<<g1, 128, SM128>>>(x,   m1_w1, m1_b1, nullptr, hb,  HID);
    gemm_rk<256, false, true,  false><<<g2, 128, SM256>>>(hb,  m1_w2, m1_b2, vp,      rs1, CCH);
    gemm_rk<128, true,  false, false><<<g1, 128, SM128>>>(rs1, m2_w1, m2_b1, nullptr, hb,  HID);
    gemm_rk<256, false, true,  true ><<<g2, 128, SM256>>>(hb,  m2_w2, m2_b2, rs1, (float*)d_out, CCH);
}

// round 16
// speedup vs baseline: 1.1676x; 1.1544x over previous
#include <cuda_runtime.h>
#include <cuda_bf16.h>
#include <cstdint>

#define NTOK 8192      // B*S
#define CCH  128       // C
#define HID  256       // 2C
#define SEQ  4096      // S per batch
#define NH   4
#define HD   32

typedef unsigned int u32;

// ---------------- scratch (static device memory, no allocs) ----------------
__device__ float g_vp [NTOK * CCH];
__device__ float g_x  [NTOK * CCH];
__device__ float g_rs1[NTOK * CCH];
__device__ float g_h  [NTOK * HID];
__device__ float g_x3 [3 * NTOK * CCH];
__device__ float g_h3 [3 * NTOK * HID];
// head-major fp16 operands: [b*NH+h][token][16 u32]
__device__ u32 g_qf[2 * NH * SEQ * 16];
__device__ u32 g_kf[2 * NH * SEQ * 16];
__device__ u32 g_vf[2 * NH * SEQ * 16];

struct Ptrs3  { const float* p[3]; };
struct LNIn   { const float* x[3]; const float* g[3]; const float* b[3]; };
struct QKVOut { u32* o16[3]; float sc[3]; float* vC; };

// ---------------- helpers -----------------------------------------------------
__device__ __forceinline__ u32 packhf(float x, float y) {      // fp16x2, x->low
    u32 d; asm("cvt.rn.f16x2.f32 %0,%2,%1;" : "=r"(d) : "f"(x), "f"(y)); return d;
}
__device__ __forceinline__ float exf(float x) {                // MUFU exp2
    float r; asm("ex2.approx.f32 %0,%1;" : "=f"(r) : "f"(x)); return r;
}
__device__ __forceinline__ u32 sptr(const void* p) {
    u32 a; asm("{.reg .u64 t; cvta.to.shared.u64 t,%1; cvt.u32.u64 %0,t;}" : "=r"(a) : "l"(p));
    return a;
}
__device__ __forceinline__ void mma16816h(float* c, const u32* a, const u32* b) {
    asm volatile(
        "mma.sync.aligned.m16n8k16.row.col.f32.f16.f16.f32 "
        "{%0,%1,%2,%3},{%4,%5,%6,%7},{%8,%9},{%0,%1,%2,%3};"
        : "+f"(c[0]), "+f"(c[1]), "+f"(c[2]), "+f"(c[3])
        : "r"(a[0]), "r"(a[1]), "r"(a[2]), "r"(a[3]), "r"(b[0]), "r"(b[1]));
}
__device__ __forceinline__ void ldsm4(u32& r0, u32& r1, u32& r2, u32& r3, u32 addr) {
    asm volatile("ldmatrix.sync.aligned.m8n8.x4.shared.b16 {%0,%1,%2,%3},[%4];"
                 : "=r"(r0), "=r"(r1), "=r"(r2), "=r"(r3) : "r"(addr));
}
__device__ __forceinline__ void ldsm4t(u32& r0, u32& r1, u32& r2, u32& r3, u32 addr) {
    asm volatile("ldmatrix.sync.aligned.m8n8.x4.trans.shared.b16 {%0,%1,%2,%3},[%4];"
                 : "=r"(r0), "=r"(r1), "=r"(r2), "=r"(r3) : "r"(addr));
}

// ---------------- LayerNorm + transpose, batched over q/k/v (R12) ------------
__global__ __launch_bounds__(256) void ln_transpose_kernel(LNIn in, float* __restrict__ y3)
{
    __shared__ float tile[CCH][17];
    const int z   = blockIdx.z;
    const float* x   = in.x[z];
    const float* gam = in.g[z];
    const float* bet = in.b[z];
    float* y = y3 + (size_t)z * NTOK * CCH;

    const int tid = threadIdx.x;
    const int s0  = blockIdx.x * 16;
    const int bb  = blockIdx.y;

    #pragma unroll
    for (int it = 0; it < 8; it++) {
        int idx = tid + it * 256;
        int c = idx >> 4, t = idx & 15;
        tile[c][t] = x[(size_t)bb * CCH * SEQ + (size_t)c * SEQ + s0 + t];
    }
    __syncthreads();

    const int w = tid >> 5, lane = tid & 31;
    #pragma unroll
    for (int rep = 0; rep < 2; rep++) {
        int t = w * 2 + rep;
        float sum = 0.f, sq = 0.f;
        #pragma unroll
        for (int j = 0; j < 4; j++) {
            float v = tile[lane + 32 * j][t];
            sum += v; sq += v * v;
        }
        #pragma unroll
        for (int off = 16; off > 0; off >>= 1) {
            sum += __shfl_xor_sync(0xffffffffu, sum, off);
            sq  += __shfl_xor_sync(0xffffffffu, sq,  off);
        }
        float mu   = sum * (1.0f / CCH);
        float var  = sq * (1.0f / CCH) - mu * mu;
        float rstd = rsqrtf(var + 1e-5f);
        size_t row = ((size_t)bb * SEQ + s0 + t) * CCH;
        #pragma unroll
        for (int j = 0; j < 4; j++) {
            int c = lane + 32 * j;
            y[row + c] = (tile[c][t] - mu) * rstd * gam[c] + bet[c];
        }
    }
}

#define AROW 12
#define BROW 36

// ---------------- single-term fp16 GEMM, batched over z (R12) ----------------
template <bool LEAKY, bool QKV>
__global__ __launch_bounds__(128, 2) void gemm_h1_kernel(
    const float* __restrict__ Abase, long Astride,
    Ptrs3 W, Ptrs3 Bi,
    float* __restrict__ Cbase, long Cstride,
    QKVOut qo, int K, int M)
{
    __shared__ __align__(16) u32 sA[2][128 * AROW];
    __shared__ __align__(16) u32 sB[2][16 * BROW];

    const int z = blockIdx.z;
    const float* A    = Abase + (size_t)z * Astride;
    const float* Bw   = W.p[z];
    const float* bias = Bi.p[z];

    const int tid  = threadIdx.x;
    const int lane = tid & 31;
    const int w    = tid >> 5;
    const int n0 = blockIdx.y * 128;
    const int m0 = blockIdx.x * 64;

    const int g  = lane >> 3;
    const int lr = lane & 7;

    int arow[4], acol[4];
    #pragma unroll
    for (int j = 0; j < 4; j++) {
        int idx = tid + 128 * j;
        arow[j] = idx >> 2;
        acol[j] = idx & 3;
    }
    int brow[2], bcol[2];
    #pragma unroll
    for (int j = 0; j < 2; j++) {
        int idx = tid + 128 * j;
        brow[j] = idx >> 4;
        bcol[j] = idx & 15;
    }

    float c[2][8][4];
    #pragma unroll
    for (int mi = 0; mi < 2; mi++)
        #pragma unroll
        for (int nt = 0; nt < 8; nt++)
            #pragma unroll
            for (int e = 0; e < 4; e++) c[mi][nt][e] = 0.f;

    const u32 bA0 = sptr(&sA[0][0]);
    const u32 bB0 = sptr(&sB[0][0]);
    const u32 abuf = 128 * AROW * 4;
    const u32 bbuf = 16 * BROW * 4;

    const int NT = K >> 4;

    float4 af[4], bf4[2];
    #pragma unroll
    for (int j = 0; j < 4; j++)
        af[j] = *reinterpret_cast<const float4*>(&A[(size_t)(n0 + arow[j]) * K + acol[j] * 4]);
    #pragma unroll
    for (int j = 0; j < 2; j++)
        bf4[j] = *reinterpret_cast<const float4*>(&Bw[(size_t)brow[j] * M + m0 + bcol[j] * 4]);

    #pragma unroll
    for (int j = 0; j < 4; j++) {
        int o = arow[j] * AROW + acol[j] * 2;
        sA[0][o]     = packhf(af[j].x, af[j].y);
        sA[0][o + 1] = packhf(af[j].z, af[j].w);
    }
    #pragma unroll
    for (int j = 0; j < 2; j++) {
        int o = brow[j] * BROW + bcol[j] * 2;
        sB[0][o]     = packhf(bf4[j].x, bf4[j].y);
        sB[0][o + 1] = packhf(bf4[j].z, bf4[j].w);
    }
    __syncthreads();

    for (int t = 0; t < NT; t++) {
        const int buf = t & 1;
        const u32 aS = bA0 + buf * abuf;
        const u32 bS = bB0 + buf * bbuf;

        if (t + 1 < NT) {
            int k0 = (t + 1) * 16;
            #pragma unroll
            for (int j = 0; j < 4; j++)
                af[j] = *reinterpret_cast<const float4*>(&A[(size_t)(n0 + arow[j]) * K + k0 + acol[j] * 4]);
            #pragma unroll
            for (int j = 0; j < 2; j++)
                bf4[j] = *reinterpret_cast<const float4*>(&Bw[(size_t)(k0 + brow[j]) * M + m0 + bcol[j] * 4]);
        }

        u32 aF[2][4];
        #pragma unroll
        for (int mi = 0; mi < 2; mi++) {
            u32 off = (u32)((w * 32 + mi * 16 + (g & 1) * 8 + lr) * 48 + (g >> 1) * 16);
            ldsm4(aF[mi][0], aF[mi][1], aF[mi][2], aF[mi][3], aS + off);
        }
        u32 bF[8][2];
        #pragma unroll
        for (int dp = 0; dp < 4; dp++) {
            u32 off = (u32)((8 * (g & 1) + lr) * 144 + (dp * 16 + 8 * (g >> 1)) * 2);
            ldsm4t(bF[2 * dp][0], bF[2 * dp][1], bF[2 * dp + 1][0], bF[2 * dp + 1][1], bS + off);
        }

        #pragma unroll
        for (int mi = 0; mi < 2; mi++)
            #pragma unroll
            for (int nt = 0; nt < 8; nt++)
                mma16816h(c[mi][nt], aF[mi], bF[nt]);

        if (t + 1 < NT) {
            const int nb = (t + 1) & 1;
            #pragma unroll
            for (int j = 0; j < 4; j++) {
                int o = arow[j] * AROW + acol[j] * 2;
                sA[nb][o]     = packhf(af[j].x, af[j].y);
                sA[nb][o + 1] = packhf(af[j].z, af[j].w);
            }
            #pragma unroll
            for (int j = 0; j < 2; j++) {
                int o = brow[j] * BROW + bcol[j] * 2;
                sB[nb][o]     = packhf(bf4[j].x, bf4[j].y);
                sB[nb][o + 1] = packhf(bf4[j].z, bf4[j].w);
            }
        }
        __syncthreads();
    }

    // ---- epilogue -----------------------------------------------------------
    #pragma unroll
    for (int mi = 0; mi < 2; mi++) {
        int r0 = n0 + w * 32 + mi * 16 + (lane >> 2);
        #pragma unroll
        for (int nt = 0; nt < 8; nt++) {
            int col = m0 + nt * 8 + (lane & 3) * 2;
            float2 bb = *reinterpret_cast<const float2*>(&bias[col]);
            float v0 = c[mi][nt][0] + bb.x;
            float v1 = c[mi][nt][1] + bb.y;
            float v2 = c[mi][nt][2] + bb.x;
            float v3 = c[mi][nt][3] + bb.y;
            if (LEAKY) {
                v0 = fmaxf(v0, 0.f) + 0.01f * fminf(v0, 0.f);
                v1 = fmaxf(v1, 0.f) + 0.01f * fminf(v1, 0.f);
                v2 = fmaxf(v2, 0.f) + 0.01f * fminf(v2, 0.f);
                v3 = fmaxf(v3, 0.f) + 0.01f * fminf(v3, 0.f);
            }
            if (!QKV) {
                float* C = Cbase + (size_t)z * Cstride;
                *reinterpret_cast<float2*>(&C[(size_t)r0 * M + col])       = make_float2(v0, v1);
                *reinterpret_cast<float2*>(&C[(size_t)(r0 + 8) * M + col]) = make_float2(v2, v3);
            } else {
                int h = col >> 5, dpair = (col & 31) >> 1;
                int bI = r0 >> 12, sI = r0 & (SEQ - 1);
                size_t oA = ((size_t)(bI * NH + h) * SEQ + sI) * 16 + dpair;
                size_t oB = oA + 8 * 16;
                u32* o16 = qo.o16[z];
                float sc = qo.sc[z];
                o16[oA] = packhf(v0 * sc, v1 * sc);
                o16[oB] = packhf(v2 * sc, v3 * sc);
                if (z == 2) {
                    *reinterpret_cast<float2*>(&qo.vC[(size_t)r0 * M + col])       = make_float2(v0, v1);
                    *reinterpret_cast<float2*>(&qo.vC[(size_t)(r0 + 8) * M + col]) = make_float2(v2, v3);
                }
            }
        }
    }
}

// ==================== resident fp16 GEMM, 64x64 tiles (R15, MLP path) =========
template <int K, bool LEAKY, bool RES, bool TRANS>
__global__ __launch_bounds__(128, (K == 128) ? 4 : 3) void gemm_rk(
    const float* __restrict__ A, const float* __restrict__ Bw,
    const float* __restrict__ bias, const float* __restrict__ res,
    float* __restrict__ C, int M)
{
    constexpr int AST = K / 2 + 4;
    constexpr int NKT = K / 16;
    extern __shared__ __align__(16) u32 dsm[];
    u32* sAf = dsm;
    u32* sB  = dsm + 64 * AST;

    const int tid  = threadIdx.x;
    const int lane = tid & 31;
    const int w    = tid >> 5;
    const int n0 = blockIdx.y * 64;
    const int m0 = blockIdx.x * 64;
    const int g  = lane >> 3;
    const int lr = lane & 7;

    #pragma unroll 8
    for (int it = 0; it < K / 8; it++) {
        int idx  = tid + it * 128;
        int row  = idx / (K / 4);
        int colq = idx % (K / 4);
        float4 f = *reinterpret_cast<const float4*>(&A[(size_t)(n0 + row) * K + colq * 4]);
        sAf[row * AST + colq * 2]     = packhf(f.x, f.y);
        sAf[row * AST + colq * 2 + 1] = packhf(f.z, f.w);
    }
    #pragma unroll 8
    for (int it = 0; it < K / 8; it++) {
        int idx  = tid + it * 128;
        int krow = idx >> 4;
        int bcol = idx & 15;
        float4 f = *reinterpret_cast<const float4*>(&Bw[(size_t)krow * M + m0 + bcol * 4]);
        int o = (krow >> 4) * 576 + (krow & 15) * 36 + bcol * 2;
        sB[o]     = packhf(f.x, f.y);
        sB[o + 1] = packhf(f.z, f.w);
    }
    __syncthreads();

    const u32 aS = sptr(sAf);
    const u32 bS = sptr(sB);
    const u32 aBase = aS + (u32)((w * 16 + (g & 1) * 8 + lr) * (AST * 4) + (g >> 1) * 16);
    const u32 bBase = bS + (u32)((8 * (g & 1) + lr) * 144);

    float c[8][4];
    #pragma unroll
    for (int nt = 0; nt < 8; nt++)
        #pragma unroll
        for (int e = 0; e < 4; e++) c[nt][e] = 0.f;

    #pragma unroll
    for (int t = 0; t < NKT; t++) {
        u32 aF[4];
        ldsm4(aF[0], aF[1], aF[2], aF[3], aBase + t * 32);
        u32 bF[8][2];
        #pragma unroll
        for (int dp = 0; dp < 4; dp++)
            ldsm4t(bF[2 * dp][0], bF[2 * dp][1], bF[2 * dp + 1][0], bF[2 * dp + 1][1],
                   bBase + t * 2304 + (dp * 16 + 8 * (g >> 1)) * 2);
        #pragma unroll
        for (int nt = 0; nt < 8; nt++)
            mma16816h(c[nt], aF, bF[nt]);
    }

    int r0 = n0 + w * 16 + (lane >> 2);
    #pragma unroll
    for (int nt = 0; nt < 8; nt++) {
        int col = m0 + nt * 8 + (lane & 3) * 2;
        float2 bb = *reinterpret_cast<const float2*>(&bias[col]);
        float v0 = c[nt][0] + bb.x;
        float v1 = c[nt][1] + bb.y;
        float v2 = c[nt][2] + bb.x;
        float v3 = c[nt][3] + bb.y;
        if (LEAKY) {
            v0 = fmaxf(v0, 0.f) + 0.01f * fminf(v0, 0.f);
            v1 = fmaxf(v1, 0.f) + 0.01f * fminf(v1, 0.f);
            v2 = fmaxf(v2, 0.f) + 0.01f * fminf(v2, 0.f);
            v3 = fmaxf(v3, 0.f) + 0.01f * fminf(v3, 0.f);
        }
        if (RES) {
            float2 r4a = *reinterpret_cast<const float2*>(&res[(size_t)r0 * M + col]);
            float2 r4b = *reinterpret_cast<const float2*>(&res[(size_t)(r0 + 8) * M + col]);
            v0 += r4a.x; v1 += r4a.y; v2 += r4b.x; v3 += r4b.y;
        }
        if (!TRANS) {
            *reinterpret_cast<float2*>(&C[(size_t)r0 * M + col])       = make_float2(v0, v1);
            *reinterpret_cast<float2*>(&C[(size_t)(r0 + 8) * M + col]) = make_float2(v2, v3);
        } else {
            int bI = r0 >> 12, sI = r0 & (SEQ - 1);
            float* dst = C + (size_t)bI * CCH * SEQ + sI;
            dst[(size_t)col * SEQ]           = v0;
            dst[(size_t)(col + 1) * SEQ]     = v1;
            dst[(size_t)col * SEQ + 8]       = v2;
            dst[(size_t)(col + 1) * SEQ + 8] = v3;
        }
    }
}

// ---------------- FA attention: unnormalized exp2 (R12, passing) -------------
#define KVT 64
#define ROWU 20

__global__ __launch_bounds__(256, 2) void attn_kernel(float* __restrict__ xo)
{
    __shared__ __align__(16) u32 skk[2][KVT * ROWU];
    __shared__ __align__(16) u32 svv[2][KVT * ROWU];

    const int tid  = threadIdx.x;
    const int lane = tid & 31;
    const int w    = tid >> 5;
    const int bh   = blockIdx.y;
    const int bb   = bh >> 2, h = bh & 3;
    const int sq0  = blockIdx.x * 128 + w * 16;

    u32 qR[2][4];
    {
        size_t qb = ((size_t)bh * SEQ + sq0 + (lane >> 2)) * 16;
        #pragma unroll
        for (int kt = 0; kt < 2; kt++) {
            int d0 = kt * 8 + (lane & 3);
            qR[kt][0] = g_qf[qb + d0];
            qR[kt][1] = g_qf[qb + 8 * 16 + d0];
            qR[kt][2] = g_qf[qb + d0 + 4];
            qR[kt][3] = g_qf[qb + 8 * 16 + d0 + 4];
        }
    }

    float o[4][4];
    #pragma unroll
    for (int dn = 0; dn < 4; dn++)
        #pragma unroll
        for (int e = 0; e < 4; e++) o[dn][e] = 0.f;
    float l0r = 0.f, l1r = 0.f;

    const int srow = tid >> 2;
    const int scq  = tid & 3;
    const size_t kvbase = (size_t)bh * SEQ * 16;

    const int g  = lane >> 3;
    const int lr = lane & 7;
    const u32 bK0 = sptr(&skk[0][0]);
    const u32 bV0 = sptr(&svv[0][0]);
    const u32 bufstride = KVT * ROWU * 4;
    const u32 ssoff = (u32)(srow * ROWU + scq * 4);

    u32 koff[2][4], voff[4][2];
    #pragma unroll
    for (int kt = 0; kt < 2; kt++)
        #pragma unroll
        for (int ap = 0; ap < 4; ap++)
            koff[kt][ap] = (u32)((16 * ap + 8 * (g >> 1) + lr) * 80 + (kt * 16 + 8 * (g & 1)) * 2);
    #pragma unroll
    for (int kt = 0; kt < 4; kt++)
        #pragma unroll
        for (int dp = 0; dp < 2; dp++)
            voff[kt][dp] = (u32)((16 * kt + 8 * (g & 1) + lr) * 80 + (dp * 16 + 8 * (g >> 1)) * 2);

    uint4 pk, pv;
    {
        size_t go = kvbase + (size_t)srow * 16 + scq * 4;
        pk = *reinterpret_cast<const uint4*>(g_kf + go);
        pv = *reinterpret_cast<const uint4*>(g_vf + go);
    }
    *reinterpret_cast<uint4*>(&skk[0][ssoff]) = pk;
    *reinterpret_cast<uint4*>(&svv[0][ssoff]) = pv;
    __syncthreads();

    const int NT = SEQ / KVT;
    for (int t = 0; t < NT; t++) {
        const int buf = t & 1;
        const u32 bK = bK0 + buf * bufstride;
        const u32 bV = bV0 + buf * bufstride;

        if (t + 1 < NT) {
            size_t go = kvbase + (size_t)((t + 1) * KVT + srow) * 16 + scq * 4;
            pk = *reinterpret_cast<const uint4*>(g_kf + go);
            pv = *reinterpret_cast<const uint4*>(g_vf + go);
        }

        float s[8][4];
        #pragma unroll
        for (int nt = 0; nt < 8; nt++)
            #pragma unroll
            for (int e = 0; e < 4; e++) s[nt][e] = 0.f;

        #pragma unroll
        for (int kt = 0; kt < 2; kt++) {
            u32 bk_[8][2];
            #pragma unroll
            for (int ap = 0; ap < 4; ap++)
                ldsm4(bk_[2 * ap][0], bk_[2 * ap][1], bk_[2 * ap + 1][0], bk_[2 * ap + 1][1],
                      bK + koff[kt][ap]);
            #pragma unroll
            for (int nt = 0; nt < 8; nt++)
                mma16816h(s[nt], qR[kt], bk_[nt]);
        }

        #pragma unroll
        for (int nt = 0; nt < 8; nt++) {
            float p0 = exf(s[nt][0]);
            float p1 = exf(s[nt][1]);
            float p2 = exf(s[nt][2]);
            float p3 = exf(s[nt][3]);
            s[nt][0] = p0; s[nt][1] = p1;
            s[nt][2] = p2; s[nt][3] = p3;
            l0r += p0 + p1;
            l1r += p2 + p3;
        }

        #pragma unroll
        for (int kt = 0; kt < 4; kt++) {
            u32 bv[4][2];
            #pragma unroll
            for (int dp = 0; dp < 2; dp++)
                ldsm4t(bv[2 * dp][0], bv[2 * dp][1], bv[2 * dp + 1][0], bv[2 * dp + 1][1],
                       bV + voff[kt][dp]);
            u32 pa[4];
            pa[0] = packhf(s[2 * kt][0],     s[2 * kt][1]);
            pa[1] = packhf(s[2 * kt][2],     s[2 * kt][3]);
            pa[2] = packhf(s[2 * kt + 1][0], s[2 * kt + 1][1]);
            pa[3] = packhf(s[2 * kt + 1][2], s[2 * kt + 1][3]);
            #pragma unroll
            for (int dn = 0; dn < 4; dn++)
                mma16816h(o[dn], pa, bv[dn]);
        }

        if (t + 1 < NT) {
            const int nb = (t + 1) & 1;
            *reinterpret_cast<uint4*>(&skk[nb][ssoff]) = pk;
            *reinterpret_cast<uint4*>(&svv[nb][ssoff]) = pv;
        }
        __syncthreads();
    }

    {
        l0r += __shfl_xor_sync(0xffffffffu, l0r, 1);
        l0r += __shfl_xor_sync(0xffffffffu, l0r, 2);
        l1r += __shfl_xor_sync(0xffffffffu, l1r, 1);
        l1r += __shfl_xor_sync(0xffffffffu, l1r, 2);
        float inv0 = 1.0f / l0r;
        float inv1 = 1.0f / l1r;
        int r = bb * SEQ + sq0 + (lane >> 2);
        #pragma unroll
        for (int dn = 0; dn < 4; dn++) {
            int cc = h * HD + dn * 8 + 2 * (lane & 3);
            float2 o0 = {o[dn][0] * inv0, o[dn][1] * inv0};
            float2 o1 = {o[dn][2] * inv1, o[dn][3] * inv1};
            *reinterpret_cast<float2*>(xo + (size_t)r * CCH + cc)       = o0;
            *reinterpret_cast<float2*>(xo + (size_t)(r + 8) * CCH + cc) = o1;
        }
    }
}

// ---------------- launch ----------------------------------------------------
static float* symf(const void* symbol) {
    void* p = nullptr;
    cudaGetSymbolAddress(&p, symbol);
    return reinterpret_cast<float*>(p);
}
static u32* symu(const void* symbol) {
    void* p = nullptr;
    cudaGetSymbolAddress(&p, symbol);
    return reinterpret_cast<u32*>(p);
}

extern "C" void kernel_launch(void* const* d_in, const int* in_sizes, int n_in,
                              void* d_out, int out_size)
{
    const float* q = (const float*)d_in[0];
    const float* k = (const float*)d_in[1];
    const float* v = (const float*)d_in[2];
    const float* ln_g[3]  = {(const float*)d_in[3],  (const float*)d_in[9],  (const float*)d_in[15]};
    const float* ln_b[3]  = {(const float*)d_in[4],  (const float*)d_in[10], (const float*)d_in[16]};
    const float* w1[3]    = {(const float*)d_in[5],  (const float*)d_in[11], (const float*)d_in[17]};
    const float* b1[3]    = {(const float*)d_in[6],  (const float*)d_in[12], (const float*)d_in[18]};
    const float* w2[3]    = {(const float*)d_in[7],  (const float*)d_in[13], (const float*)d_in[19]};
    const float* b2[3]    = {(const float*)d_in[8],  (const float*)d_in[14], (const float*)d_in[20]};
    const float* m1_w1 = (const float*)d_in[21];
    const float* m1_b1 = (const float*)d_in[22];
    const float* m1_w2 = (const float*)d_in[23];
    const float* m1_b2 = (const float*)d_in[24];
    const float* m2_w1 = (const float*)d_in[25];
    const float* m2_b1 = (const float*)d_in[26];
    const float* m2_w2 = (const float*)d_in[27];
    const float* m2_b2 = (const float*)d_in[28];

    float* vp  = symf(g_vp);
    float* x   = symf(g_x);
    float* rs1 = symf(g_rs1);
    float* hb  = symf(g_h);
    float* x3  = symf(g_x3);
    float* h3  = symf(g_h3);
    u32* qf = symu(g_qf);
    u32* kf = symu(g_kf);
    u32* vf = symu(g_vf);

    const float qsc = 1.44269504088896f / 5.65685424949238f;  // log2e/sqrt(32)

    // dynamic smem sizes (64-row tiles for MLP)
    const int SM128 = (64 * 68 + 8 * 576) * 4;      // 35840
    const int SM256 = (64 * 132 + 16 * 576) * 4;    // 70656

    cudaFuncSetAttribute(gemm_rk<128, true,  false, false>,
                         cudaFuncAttributeMaxDynamicSharedMemorySize, SM128);
    cudaFuncSetAttribute(gemm_rk<256, false, true,  false>,
                         cudaFuncAttributeMaxDynamicSharedMemorySize, SM256);
    cudaFuncSetAttribute(gemm_rk<256, false, true,  true>,
                         cudaFuncAttributeMaxDynamicSharedMemorySize, SM256);

    // ---- batched LN for q,k,v (R12) ----
    LNIn lp;
    lp.x[0] = q; lp.x[1] = k; lp.x[2] = v;
    for (int i = 0; i < 3; i++) { lp.g[i] = ln_g[i]; lp.b[i] = ln_b[i]; }
    ln_transpose_kernel<<<dim3(SEQ / 16, 2, 3), 256>>>(lp, x3);

    // ---- batched GEMM1 (C->2C, LeakyReLU) (R12) ----
    Ptrs3 W1 = {{w1[0], w1[1], w1[2]}};
    Ptrs3 B1 = {{b1[0], b1[1], b1[2]}};
    QKVOut dummy = {{nullptr, nullptr, nullptr}, {0.f, 0.f, 0.f}, nullptr};
    gemm_h1_kernel<true, false><<<dim3(HID / 64, NTOK / 128, 3), 128>>>(
        x3, (long)NTOK * CCH, W1, B1, h3, (long)NTOK * HID, dummy, CCH, HID);

    // ---- batched GEMM2 (2C->C, fp16 head-major; v also fp32) (R12) ----
    Ptrs3 W2 = {{w2[0], w2[1], w2[2]}};
    Ptrs3 B2 = {{b2[0], b2[1], b2[2]}};
    QKVOut qo = {{qf, kf, vf}, {qsc, 1.f, 1.f}, vp};
    gemm_h1_kernel<false, true><<<dim3(CCH / 64, NTOK / 128, 3), 128>>>(
        h3, (long)NTOK * HID, W2, B2, nullptr, 0, qo, HID, CCH);

    // ---- attention (R12) ----
    attn_kernel<<<dim3(SEQ / 128, 2 * NH), 256>>>(x);

    // ---- MLPs (64x64 resident tiles); last writes [B,C,S] directly ----
    dim3 g1(HID / 64, NTOK / 64);   // (4, 128) = 512 CTAs
    dim3 g2(CCH / 64, NTOK / 64);   // (2, 128) = 256 CTAs
    gemm_rk<128, true,  false, false><<<g1, 128, SM128>>>(x,   m1_w1, m1_b1, nullptr, hb,  HID);
    gemm_rk<256, false, true,  false><<<g2, 128, SM256>>>(hb,  m1_w2, m1_b2, vp,      rs1, CCH);
    gemm_rk<128, true,  false, false><<<g1, 128, SM128>>>(rs1, m2_w1, m2_b1, nullptr, hb,  HID);
    gemm_rk<256, false, true,  true ><<<g2, 128, SM256>>>(hb,  m2_w2, m2_b2, rs1, (float*)d_out, CCH);
}